// round 1
// baseline (speedup 1.0000x reference)
#include <cuda_runtime.h>
#include <cuda_bf16.h>
#include <math.h>

// Problem constants (fixed by the reference)
#define Bc   4
#define Pc   1024
#define Dc   512
#define Hc   8
#define DKc  64
#define HALFW 32           // SPARSITY/2
#define CONCAT_P (2*Pc)    // 2048

// Scratch (no cudaMalloc allowed)
__device__ float g_Q[Bc * Pc * Dc];          // 2M floats
__device__ float g_K[Bc * Pc * Dc];
__device__ float g_V[Bc * Pc * Dc];
__device__ float g_concat[Bc * CONCAT_P * Dc]; // 4M floats

// ---------------------------------------------------------------------------
// Tiled fp32 GEMM + bias: C[M,N] = A[M,K] @ W[K,N] + bias[N]
// BM=BN=64, BK=16, 256 threads, 4x4 register tile per thread.
// ---------------------------------------------------------------------------
__global__ __launch_bounds__(256)
void gemm_bias_kernel(const float* __restrict__ A, const float* __restrict__ W,
                      const float* __restrict__ bias, float* __restrict__ C,
                      int M, int N, int K)
{
    const int BM = 64, BN = 64, BK = 16;
    __shared__ float As[BK][BM + 4];   // transposed A tile; pad keeps float4 align (68%4==0)
    __shared__ float Ws[BK][BN + 4];

    int tid = threadIdx.x;
    int tx = tid & 15;        // N direction
    int ty = tid >> 4;        // M direction
    int row0 = blockIdx.y * BM;
    int col0 = blockIdx.x * BN;

    float acc[4][4];
#pragma unroll
    for (int i = 0; i < 4; i++)
#pragma unroll
        for (int j = 0; j < 4; j++) acc[i][j] = 0.f;

    for (int k0 = 0; k0 < K; k0 += BK) {
        // Load A tile (64 rows x 16 cols) transposed into As[k][m]
#pragma unroll
        for (int i = 0; i < 4; i++) {
            int e = tid + i * 256;          // 0..1023
            int m = e >> 4;
            int kk = e & 15;
            As[kk][m] = A[(long long)(row0 + m) * K + (k0 + kk)];
        }
        // Load W tile (16 rows x 64 cols) into Ws[k][n]
#pragma unroll
        for (int i = 0; i < 4; i++) {
            int e = tid + i * 256;          // 0..1023
            int kk = e >> 6;
            int n = e & 63;
            Ws[kk][n] = W[(long long)(k0 + kk) * N + (col0 + n)];
        }
        __syncthreads();

#pragma unroll
        for (int kk = 0; kk < BK; kk++) {
            float4 a4 = *(const float4*)&As[kk][ty * 4];
            float4 b4 = *(const float4*)&Ws[kk][tx * 4];
            float ar[4] = {a4.x, a4.y, a4.z, a4.w};
            float br[4] = {b4.x, b4.y, b4.z, b4.w};
#pragma unroll
            for (int i = 0; i < 4; i++)
#pragma unroll
                for (int j = 0; j < 4; j++)
                    acc[i][j] = fmaf(ar[i], br[j], acc[i][j]);
        }
        __syncthreads();
    }

#pragma unroll
    for (int i = 0; i < 4; i++) {
        long long rbase = (long long)(row0 + ty * 4 + i) * N + col0;
#pragma unroll
        for (int j = 0; j < 4; j++) {
            int n = tx * 4 + j;
            C[rbase + n] = acc[i][j] + bias[col0 + n];
        }
    }
}

// ---------------------------------------------------------------------------
// Banded attention, one block per (b, h, i) query row. 128 threads.
// Computes out row into g_concat[b, rowOffset+i, h*64 + :] and (optionally)
// writes the full dense attention row A[b,h,i,:] (zeros outside band).
// ---------------------------------------------------------------------------
__global__ __launch_bounds__(128)
void attn_band_kernel(const float* __restrict__ Qp, const float* __restrict__ Kp,
                      const float* __restrict__ Vp, float* __restrict__ concatOut,
                      int rowOffset, float* __restrict__ Aout)
{
    int i = blockIdx.x;
    int h = blockIdx.y;
    int b = blockIdx.z;
    int tid = threadIdx.x;

    __shared__ float qs[DKc];
    __shared__ float ks[65 * 65];   // padded rows: bank-conflict free
    __shared__ float vs[65 * 65];
    __shared__ float sc[65];

    int jlo = i - HALFW; if (jlo < 0) jlo = 0;
    int jhi = i + HALFW; if (jhi > Pc - 1) jhi = Pc - 1;
    int cnt = jhi - jlo + 1;
    const float scale = 0.125f;  // 1/sqrt(64)

    long long headBase = (long long)b * Pc * Dc + (long long)h * DKc;

    if (tid < DKc) qs[tid] = Qp[headBase + (long long)i * Dc + tid];
    for (int e = tid; e < cnt * DKc; e += 128) {
        int r = e >> 6;
        int d = e & 63;
        long long src = headBase + (long long)(jlo + r) * Dc + d;
        ks[r * 65 + d] = Kp[src];
        vs[r * 65 + d] = Vp[src];
    }
    __syncthreads();

    // Scores
    if (tid < cnt) {
        float s = 0.f;
#pragma unroll 16
        for (int d = 0; d < DKc; d++) s = fmaf(qs[d], ks[tid * 65 + d], s);
        sc[tid] = s;
    }
    __syncthreads();

    // Max (redundant per-thread scan over <=65 smem values: broadcast reads)
    float m = -1e30f;
    for (int j = 0; j < cnt; j++) m = fmaxf(m, sc[j]);

    float myp = 0.f;
    if (tid < cnt) myp = expf(scale * (sc[tid] - m));
    __syncthreads();               // everyone done reading raw scores
    if (tid < cnt) sc[tid] = myp;
    __syncthreads();

    float ssum = 0.f;
    for (int j = 0; j < cnt; j++) ssum += sc[j];
    float inv = 1.0f / ssum;

    // Output row: thread t owns channel d = t
    if (tid < DKc) {
        float acc = 0.f;
        for (int j = 0; j < cnt; j++) acc = fmaf(sc[j], vs[j * 65 + tid], acc);
        concatOut[((long long)b * CONCAT_P + rowOffset + i) * Dc + h * DKc + tid] = acc * inv;
    }

    // Dense attention row (zeros outside band)
    if (Aout) {
        long long arow = (((long long)b * Hc + h) * Pc + i) * (long long)Pc;
        for (int j = tid; j < Pc; j += 128) {
            float v = 0.f;
            if (j >= jlo && j <= jhi) v = sc[j - jlo] * inv;
            Aout[arow + j] = v;
        }
    }
}

// ---------------------------------------------------------------------------
// kernel_launch
// Inputs (metadata order): queries, keys, values, Wq, bq, Wk, bk, Wv, bv,
//                          Wo, bo, num_patches
// Output tuple (flattened): out (4*2048*512), A1 (4*8*1024*1024), A2 (same)
// ---------------------------------------------------------------------------
extern "C" void kernel_launch(void* const* d_in, const int* in_sizes, int n_in,
                              void* d_out, int out_size)
{
    const float* queries = (const float*)d_in[0];
    const float* keys    = (const float*)d_in[1];
    const float* values  = (const float*)d_in[2];
    const float* Wq = (const float*)d_in[3];
    const float* bq = (const float*)d_in[4];
    const float* Wk = (const float*)d_in[5];
    const float* bk = (const float*)d_in[6];
    const float* Wv = (const float*)d_in[7];
    const float* bv = (const float*)d_in[8];
    const float* Wo = (const float*)d_in[9];
    const float* bo = (const float*)d_in[10];

    float* out = (float*)d_out;

    float *Qb, *Kb, *Vb, *Cb;
    cudaGetSymbolAddress((void**)&Qb, g_Q);
    cudaGetSymbolAddress((void**)&Kb, g_K);
    cudaGetSymbolAddress((void**)&Vb, g_V);
    cudaGetSymbolAddress((void**)&Cb, g_concat);

    const int M1 = Bc * Pc;        // 4096
    const int M2 = Bc * CONCAT_P;  // 8192
    const int N = Dc, K = Dc;      // 512

    dim3 g1(N / 64, M1 / 64);
    gemm_bias_kernel<<<g1, 256>>>(queries, Wq, bq, Qb, M1, N, K);
    gemm_bias_kernel<<<g1, 256>>>(keys,    Wk, bk, Kb, M1, N, K);
    gemm_bias_kernel<<<g1, 256>>>(values,  Wv, bv, Vb, M1, N, K);

    // Does d_out hold the full tuple (out, A1, A2)?
    const long long mainN = (long long)Bc * CONCAT_P * Dc;          // 4,194,304
    const long long aN    = (long long)Bc * Hc * Pc * Pc;           // 33,554,432
    float* A1 = nullptr;
    float* A2 = nullptr;
    if ((long long)out_size >= mainN + 2 * aN) {
        A1 = out + mainN;
        A2 = A1 + aN;
    }

    dim3 ga(Pc, Hc, Bc);
    // attention 1: (q, k, v)
    attn_band_kernel<<<ga, 128>>>(Qb, Kb, Vb, Cb, 0,  A1);
    // attention 2: (k, q, q)
    attn_band_kernel<<<ga, 128>>>(Kb, Qb, Qb, Cb, Pc, A2);

    dim3 g2(N / 64, M2 / 64);
    gemm_bias_kernel<<<g2, 256>>>(Cb, Wo, bo, out, M2, N, K);
}

// round 2
// speedup vs baseline: 1.5249x; 1.5249x over previous
#include <cuda_runtime.h>
#include <cuda_bf16.h>
#include <math.h>

#define Bc   4
#define Pc   1024
#define Dc   512
#define Hc   8
#define DKc  64
#define HALFW 32
#define CONCAT_P (2*Pc)

__device__ float g_Q[Bc * Pc * Dc];
__device__ float g_K[Bc * Pc * Dc];
__device__ float g_V[Bc * Pc * Dc];
__device__ float g_concat[Bc * CONCAT_P * Dc];

// ---------------------------------------------------------------------------
// Zero-fill kernel (for A1/A2 regions): float4 grid-stride
// ---------------------------------------------------------------------------
__global__ void zero_kernel(float4* __restrict__ p, long long n4)
{
    long long idx = (long long)blockIdx.x * blockDim.x + threadIdx.x;
    long long stride = (long long)gridDim.x * blockDim.x;
    float4 z = make_float4(0.f, 0.f, 0.f, 0.f);
    for (long long i = idx; i < n4; i += stride) p[i] = z;
}

// ---------------------------------------------------------------------------
// 128x128x8 fp32 GEMM + bias, 256 threads, 8x8 microtile.
// C[M,N] = A[M,K] @ W[K,N] + bias[N]
// ---------------------------------------------------------------------------
struct GemmArgs { const float* A; const float* W; const float* bias; float* C; };

__device__ __forceinline__
void gemm_body(const float* __restrict__ A, const float* __restrict__ W,
               const float* __restrict__ bias, float* __restrict__ C,
               int M, int N, int K)
{
    __shared__ float As[8 * 132];   // As[k][m], stride 132
    __shared__ float Ws[8 * 132];   // Ws[k][n], stride 132

    int tid = threadIdx.x;
    int tx = tid & 15;   // n block
    int ty = tid >> 4;   // m block
    int row0 = blockIdx.y * 128;
    int col0 = blockIdx.x * 128;

    // A load indices: each thread one float4
    int a_row = tid >> 1;          // 0..127
    int a_kq  = (tid & 1) * 4;     // 0 or 4
    // W load indices
    int w_r = tid >> 5;            // 0..7
    int w_c = (tid & 31) * 4;      // 0..124

    float acc[8][8];
#pragma unroll
    for (int i = 0; i < 8; i++)
#pragma unroll
        for (int j = 0; j < 8; j++) acc[i][j] = 0.f;

    for (int k0 = 0; k0 < K; k0 += 8) {
        float4 av = *(const float4*)&A[(long long)(row0 + a_row) * K + k0 + a_kq];
        float4 wv = *(const float4*)&W[(long long)(k0 + w_r) * N + col0 + w_c];
        // transpose-store A
        As[(a_kq + 0) * 132 + a_row] = av.x;
        As[(a_kq + 1) * 132 + a_row] = av.y;
        As[(a_kq + 2) * 132 + a_row] = av.z;
        As[(a_kq + 3) * 132 + a_row] = av.w;
        *(float4*)&Ws[w_r * 132 + w_c] = wv;
        __syncthreads();

#pragma unroll
        for (int k = 0; k < 8; k++) {
            float4 a0 = *(const float4*)&As[k * 132 + ty * 8];
            float4 a1 = *(const float4*)&As[k * 132 + ty * 8 + 4];
            float4 b0 = *(const float4*)&Ws[k * 132 + tx * 8];
            float4 b1 = *(const float4*)&Ws[k * 132 + tx * 8 + 4];
            float ar[8] = {a0.x, a0.y, a0.z, a0.w, a1.x, a1.y, a1.z, a1.w};
            float br[8] = {b0.x, b0.y, b0.z, b0.w, b1.x, b1.y, b1.z, b1.w};
#pragma unroll
            for (int i = 0; i < 8; i++)
#pragma unroll
                for (int j = 0; j < 8; j++)
                    acc[i][j] = fmaf(ar[i], br[j], acc[i][j]);
        }
        __syncthreads();
    }

    float4 bia = *(const float4*)&bias[col0 + tx * 8];
    float4 bib = *(const float4*)&bias[col0 + tx * 8 + 4];
#pragma unroll
    for (int i = 0; i < 8; i++) {
        long long rbase = (long long)(row0 + ty * 8 + i) * N + col0 + tx * 8;
        float4 o0 = make_float4(acc[i][0] + bia.x, acc[i][1] + bia.y,
                                acc[i][2] + bia.z, acc[i][3] + bia.w);
        float4 o1 = make_float4(acc[i][4] + bib.x, acc[i][5] + bib.y,
                                acc[i][6] + bib.z, acc[i][7] + bib.w);
        *(float4*)&C[rbase]     = o0;
        *(float4*)&C[rbase + 4] = o1;
    }
}

__global__ __launch_bounds__(256)
void gemm_bias_kernel(GemmArgs g, int M, int N, int K)
{
    gemm_body(g.A, g.W, g.bias, g.C, M, N, K);
}

__global__ __launch_bounds__(256)
void gemm3_bias_kernel(GemmArgs g0, GemmArgs g1, GemmArgs g2, int M, int N, int K)
{
    GemmArgs g = (blockIdx.z == 0) ? g0 : (blockIdx.z == 1) ? g1 : g2;
    gemm_body(g.A, g.W, g.bias, g.C, M, N, K);
}

// ---------------------------------------------------------------------------
// Tiled banded attention: block = 64 queries of one (b,h). 256 threads.
// S = Q*K^T (64x128), masked softmax, O = P*V (64x64). Writes band entries
// of A (dense A was pre-zeroed) and the O tile into concat buffer.
// Dynamic smem layout (floats):
//   Qs[64][68]   (Qs[d][qi])            off 0      size 4352
//   Ks[64][132]  (Ks[d][kj])            off 4352   size 8448
//   Ss[64][132]  (Ss[qi][kj])           off 12800  size 8448
//   Vs[128][68]  (Vs[kj][d])            off 21248  size 8704
//   sinv[64]                            off 29952  size 64
// total 30016 floats = 120064 bytes
// ---------------------------------------------------------------------------
#define SM_QS 0
#define SM_KS 4352
#define SM_SS 12800
#define SM_VS 21248
#define SM_INV 29952
#define ATTN_SMEM_BYTES (30016 * 4)

__global__ __launch_bounds__(256)
void attn_tile_kernel(const float* __restrict__ Qp, const float* __restrict__ Kp,
                      const float* __restrict__ Vp, float* __restrict__ concatOut,
                      int rowOffset, float* __restrict__ Aout)
{
    extern __shared__ float sm[];
    float* Qs = sm + SM_QS;
    float* Ks = sm + SM_KS;
    float* Ss = sm + SM_SS;
    float* Vs = sm + SM_VS;
    float* sinv = sm + SM_INV;

    int tid = threadIdx.x;
    int q0 = blockIdx.x * 64;
    int h  = blockIdx.y;
    int b  = blockIdx.z;
    int k0 = q0 - HALFW;                       // key tile start (may be <0)
    const float scale = 0.125f;

    long long headBase = (long long)b * Pc * Dc + (long long)h * DKc;

    // Load Q tile (64 rows x 64 d), transposed into Qs[d][qi]
    {
        int r = tid >> 2;          // 0..63
        int c = (tid & 3) * 16;    // 0,16,32,48
#pragma unroll
        for (int cc = 0; cc < 16; cc += 4) {
            float4 v = *(const float4*)&Qp[headBase + (long long)(q0 + r) * Dc + c + cc];
            Qs[(c + cc + 0) * 68 + r] = v.x;
            Qs[(c + cc + 1) * 68 + r] = v.y;
            Qs[(c + cc + 2) * 68 + r] = v.z;
            Qs[(c + cc + 3) * 68 + r] = v.w;
        }
    }
    // Load K (transposed) and V (direct) tiles: 128 rows x 64 d
    for (int t = tid; t < 128 * 16; t += 256) {
        int r = t >> 4;            // 0..127
        int c = (t & 15) * 4;      // 0..60
        int j = k0 + r;
        float4 kv = make_float4(0.f, 0.f, 0.f, 0.f);
        float4 vv = kv;
        if (j >= 0 && j < Pc) {
            long long src = headBase + (long long)j * Dc + c;
            kv = *(const float4*)&Kp[src];
            vv = *(const float4*)&Vp[src];
        }
        Ks[(c + 0) * 132 + r] = kv.x;
        Ks[(c + 1) * 132 + r] = kv.y;
        Ks[(c + 2) * 132 + r] = kv.z;
        Ks[(c + 3) * 132 + r] = kv.w;
        *(float4*)&Vs[r * 68 + c] = vv;
    }
    __syncthreads();

    // GEMM1: S[64][128] = Q(64x64) * K^T(64x128); thread -> 4(qi) x 8(kj)
    int tx = tid & 15;   // kj block
    int ty = tid >> 4;   // qi block
    {
        float acc[4][8];
#pragma unroll
        for (int i = 0; i < 4; i++)
#pragma unroll
            for (int j = 0; j < 8; j++) acc[i][j] = 0.f;

#pragma unroll 4
        for (int d = 0; d < 64; d++) {
            float4 a = *(const float4*)&Qs[d * 68 + ty * 4];
            float4 b0 = *(const float4*)&Ks[d * 132 + tx * 8];
            float4 b1 = *(const float4*)&Ks[d * 132 + tx * 8 + 4];
            float ar[4] = {a.x, a.y, a.z, a.w};
            float br[8] = {b0.x, b0.y, b0.z, b0.w, b1.x, b1.y, b1.z, b1.w};
#pragma unroll
            for (int i = 0; i < 4; i++)
#pragma unroll
                for (int j = 0; j < 8; j++)
                    acc[i][j] = fmaf(ar[i], br[j], acc[i][j]);
        }
#pragma unroll
        for (int i = 0; i < 4; i++) {
            int row = ty * 4 + i;
            *(float4*)&Ss[row * 132 + tx * 8] =
                make_float4(acc[i][0], acc[i][1], acc[i][2], acc[i][3]);
            *(float4*)&Ss[row * 132 + tx * 8 + 4] =
                make_float4(acc[i][4], acc[i][5], acc[i][6], acc[i][7]);
        }
    }
    __syncthreads();

    // Softmax per query row (threads 0..63)
    if (tid < 64) {
        int qi = tid;
        int i = q0 + qi;
        int jlo = i - HALFW; if (jlo < 0) jlo = 0;
        int jhi = i + HALFW; if (jhi > Pc - 1) jhi = Pc - 1;
        int kjlo = jlo - k0;
        int kjhi = jhi - k0;
        float* srow = &Ss[qi * 132];

        float m = -1e30f;
        for (int kj = kjlo; kj <= kjhi; kj++) m = fmaxf(m, srow[kj]);
        float sum = 0.f;
        for (int kj = 0; kj < 128; kj++) {
            float p = 0.f;
            if (kj >= kjlo && kj <= kjhi) {
                p = __expf(scale * (srow[kj] - m));
                sum += p;
            }
            srow[kj] = p;
        }
        sinv[qi] = 1.0f / sum;
    }
    __syncthreads();

    // Band write into dense A (pre-zeroed)
    if (Aout) {
        for (int t = tid; t < 64 * 65; t += 256) {
            int qi = t / 65;
            int off = t - qi * 65;
            int i = q0 + qi;
            int jlo = i - HALFW; if (jlo < 0) jlo = 0;
            int jhi = i + HALFW; if (jhi > Pc - 1) jhi = Pc - 1;
            if (off <= jhi - jlo) {
                int j = jlo + off;
                int kj = j - k0;
                long long arow = (((long long)b * Hc + h) * Pc + i) * (long long)Pc;
                Aout[arow + j] = Ss[qi * 132 + kj] * sinv[qi];
            }
        }
    }

    // GEMM2: O[64][64] = P(64x128) * V(128x64); thread -> 4(qi) x 4(d)
    {
        int txd = tid & 15;   // d block
        int tyq = tid >> 4;   // qi block
        float acc[4][4];
#pragma unroll
        for (int i = 0; i < 4; i++)
#pragma unroll
            for (int j = 0; j < 4; j++) acc[i][j] = 0.f;

#pragma unroll 4
        for (int kj = 0; kj < 128; kj++) {
            float4 bv = *(const float4*)&Vs[kj * 68 + txd * 4];
            float br[4] = {bv.x, bv.y, bv.z, bv.w};
#pragma unroll
            for (int i = 0; i < 4; i++) {
                float a = Ss[(tyq * 4 + i) * 132 + kj];
#pragma unroll
                for (int j = 0; j < 4; j++)
                    acc[i][j] = fmaf(a, br[j], acc[i][j]);
            }
        }
#pragma unroll
        for (int i = 0; i < 4; i++) {
            int qi = tyq * 4 + i;
            float inv = sinv[qi];
            long long dst = ((long long)b * CONCAT_P + rowOffset + q0 + qi) * Dc
                            + h * DKc + txd * 4;
            *(float4*)&concatOut[dst] = make_float4(acc[i][0] * inv, acc[i][1] * inv,
                                                    acc[i][2] * inv, acc[i][3] * inv);
        }
    }
}

// ---------------------------------------------------------------------------
extern "C" void kernel_launch(void* const* d_in, const int* in_sizes, int n_in,
                              void* d_out, int out_size)
{
    const float* queries = (const float*)d_in[0];
    const float* keys    = (const float*)d_in[1];
    const float* values  = (const float*)d_in[2];
    const float* Wq = (const float*)d_in[3];
    const float* bq = (const float*)d_in[4];
    const float* Wk = (const float*)d_in[5];
    const float* bk = (const float*)d_in[6];
    const float* Wv = (const float*)d_in[7];
    const float* bv = (const float*)d_in[8];
    const float* Wo = (const float*)d_in[9];
    const float* bo = (const float*)d_in[10];

    float* out = (float*)d_out;

    float *Qb, *Kb, *Vb, *Cb;
    cudaGetSymbolAddress((void**)&Qb, g_Q);
    cudaGetSymbolAddress((void**)&Kb, g_K);
    cudaGetSymbolAddress((void**)&Vb, g_V);
    cudaGetSymbolAddress((void**)&Cb, g_concat);

    static int attr_set = 0;
    if (!attr_set) {
        cudaFuncSetAttribute(attn_tile_kernel,
                             cudaFuncAttributeMaxDynamicSharedMemorySize,
                             ATTN_SMEM_BYTES);
        attr_set = 1;
    }

    const int M1 = Bc * Pc;        // 4096
    const int M2 = Bc * CONCAT_P;  // 8192
    const int N = Dc, K = Dc;

    const long long mainN = (long long)Bc * CONCAT_P * Dc;   // 4,194,304
    const long long aN    = (long long)Bc * Hc * Pc * Pc;    // 33,554,432
    float* A1 = nullptr;
    float* A2 = nullptr;
    bool hasA = ((long long)out_size >= mainN + 2 * aN);
    if (hasA) {
        A1 = out + mainN;
        A2 = A1 + aN;
        // zero both A regions (contiguous)
        long long n4 = (2 * aN) / 4;
        zero_kernel<<<4096, 256>>>((float4*)A1, n4);
    }

    // 3 projection GEMMs in one launch
    GemmArgs gq = {queries, Wq, bq, Qb};
    GemmArgs gk = {keys,    Wk, bk, Kb};
    GemmArgs gv = {values,  Wv, bv, Vb};
    dim3 g1(N / 128, M1 / 128, 3);
    gemm3_bias_kernel<<<g1, 256>>>(gq, gk, gv, M1, N, K);

    dim3 ga(Pc / 64, Hc, Bc);
    attn_tile_kernel<<<ga, 256, ATTN_SMEM_BYTES>>>(Qb, Kb, Vb, Cb, 0,  A1);
    attn_tile_kernel<<<ga, 256, ATTN_SMEM_BYTES>>>(Kb, Qb, Qb, Cb, Pc, A2);

    GemmArgs go = {Cb, Wo, bo, out};
    dim3 g2(N / 128, M2 / 128, 1);
    gemm_bias_kernel<<<g2, 256>>>(go, M2, N, K);
}